// round 12
// baseline (speedup 1.0000x reference)
#include <cuda_runtime.h>
#include <cstdint>

#define Bq 4
#define T 128
#define D 300
#define D4 75            // D / 4 (float4 count per row)

// Scratch for projected q (rows 0..511), k (512..1023), v (1024..1535)
__device__ __align__(16) float g_qkv[3 * Bq * T * D];

// ---------------------------------------------------------------------------
// Kernel 1: batched projection GEMM — round-10 version (best measured).
// 32x32 tiles, 128 threads, 4x2 microtile, k-chunk 32, double-buffered,
// swizzled smem. Grid (10, 48) = 480 CTAs.
// out[r,c] = A[r,:] . W[c,:] + bias[c]
// rows 0..511 -> query/WQ/bQ, 512..1023 -> key/WK/bK, 1024..1535 -> value/WK/bK
// ---------------------------------------------------------------------------
__global__ __launch_bounds__(128) void proj_kernel(
    const float* __restrict__ query, const float* __restrict__ key,
    const float* __restrict__ value,
    const float* __restrict__ WQ, const float* __restrict__ bQ,
    const float* __restrict__ WK, const float* __restrict__ bK)
{
    __shared__ float A_s[2][32][36];
    __shared__ float W_s[2][32][36];

    const int row0 = blockIdx.y * 32;
    const int col0 = blockIdx.x * 32;
    const int tid  = threadIdx.x;
    const int tx   = tid & 15;    // 16 col groups x 2 cols
    const int ty   = tid >> 4;    // 8 row groups x 4 rows

    const int sel = row0 >> 9;    // 0: query, 1: key, 2: value
    const float* Ap = (sel == 0) ? query : (sel == 1 ? key : value);
    const float* Wp = (sel == 0) ? WQ : WK;
    const float* bp = (sel == 0) ? bQ : bK;
    const int arow0 = row0 & 511;

    const int lm = tid >> 3;          // 0..15
    const int lk = (tid & 7) * 4;     // 0,4,..,28

    const int NC = (D + 31) / 32;     // 10 chunks
    float4 a_r[2], w_r[2];

    auto fetch = [&](int k0) {
        bool kv = (k0 + lk) < D;      // D%4==0: float4 never straddles
#pragma unroll
        for (int p = 0; p < 2; p++) {
            int r = lm + p * 16;
            a_r[p] = kv ? *(const float4*)&Ap[(arow0 + r) * D + k0 + lk]
                        : make_float4(0.f, 0.f, 0.f, 0.f);
            int gc = col0 + r;
            w_r[p] = (kv && gc < D) ? *(const float4*)&Wp[gc * D + k0 + lk]
                                    : make_float4(0.f, 0.f, 0.f, 0.f);
        }
    };
    auto store = [&](int buf) {
#pragma unroll
        for (int p = 0; p < 2; p++) {
            int r   = lm + p * 16;
            int col = (r + lk) & 31;          // swizzle
            A_s[buf][lk + 0][col] = a_r[p].x; A_s[buf][lk + 1][col] = a_r[p].y;
            A_s[buf][lk + 2][col] = a_r[p].z; A_s[buf][lk + 3][col] = a_r[p].w;
            W_s[buf][lk + 0][col] = w_r[p].x; W_s[buf][lk + 1][col] = w_r[p].y;
            W_s[buf][lk + 2][col] = w_r[p].z; W_s[buf][lk + 3][col] = w_r[p].w;
        }
    };

    float acc[4][2];
#pragma unroll
    for (int r = 0; r < 4; r++) { acc[r][0] = 0.f; acc[r][1] = 0.f; }

    fetch(0);
    store(0);
    __syncthreads();

    for (int ch = 0; ch < NC; ch++) {
        const int buf = ch & 1;
        if (ch + 1 < NC) fetch((ch + 1) * 32);
#pragma unroll
        for (int e = 0; e < 32; e++) {
            const int off = e & ~3;
            float4 av = *(const float4*)&A_s[buf][e][(ty * 4 + off) & 31];
            float2 wv = *(const float2*)&W_s[buf][e][(tx * 2 + off) & 31];
            acc[0][0] += av.x * wv.x; acc[0][1] += av.x * wv.y;
            acc[1][0] += av.y * wv.x; acc[1][1] += av.y * wv.y;
            acc[2][0] += av.z * wv.x; acc[2][1] += av.z * wv.y;
            acc[3][0] += av.w * wv.x; acc[3][1] += av.w * wv.y;
        }
        if (ch + 1 < NC) store(1 - buf);
        __syncthreads();
    }

#pragma unroll
    for (int r = 0; r < 4; r++) {
        int gr = row0 + ty * 4 + r;
#pragma unroll
        for (int c = 0; c < 2; c++) {
            int gcol = col0 + tx * 2 + c;
            if (gcol < D) g_qkv[gr * D + gcol] = acc[r][c] + bp[gcol];
        }
    }
}

// ---------------------------------------------------------------------------
// Kernel 2: fused attention — round-10 code, but 5 CTAs/SM (40 warps/SM,
// 48-reg ceiling) to push aggregate MLP / HBM throughput further up the
// warp-scaling curve measured across rounds.
// ---------------------------------------------------------------------------
__global__ __launch_bounds__(256, 5) void attn_kernel(
    const float* __restrict__ hL, const float* __restrict__ hR,
    float* __restrict__ out)
{
    __shared__ float q_s[304];
    __shared__ float scores_s[128];
    __shared__ float listw_s[128];
    __shared__ int   listj_s[128];
    __shared__ int   cnt_s;

    const int tid  = threadIdx.x;
    const int lane = tid & 31;
    const int w    = tid >> 5;           // 8 warps
    const int b    = blockIdx.x >> 7;
    const int i    = blockIdx.x & 127;

    const float4* qkv4 = (const float4*)g_qkv;

    // ---- load q_i (L2-hot, tiny) ----
    if (tid < D4) ((float4*)q_s)[tid] = qkv4[(b * T + i) * D4 + tid];
    __syncthreads();

    const float4* q4 = (const float4*)q_s;
    const bool has_c = (lane < D4 - 64);           // lane < 11

    // ---- scoring: scores_j = sum_d (q[d]+hL[b,i,j,d]) * (k[b,j,d]+hR[b,j,i,d])
    const float4* hL4 = (const float4*)hL + (size_t)(b * T + i) * T * D4;
    const float4* hRb = (const float4*)hR + ((size_t)b * T * T + i) * D4;
    const float4* k4b = qkv4 + (Bq * T + b * T) * D4;

#pragma unroll 2
    for (int jj = 0; jj < 16; jj++) {
        const int j = w * 16 + jj;
        const float4* hl = hL4 + j * D4;
        const float4* hr = hRb + (size_t)j * T * D4;
        const float4* kp = k4b + j * D4;

        float4 l0 = hl[lane],      r0 = hr[lane],      k0 = kp[lane];
        float4 l1 = hl[lane + 32], r1 = hr[lane + 32], k1 = kp[lane + 32];
        float4 l2, r2, k2;
        if (has_c) { l2 = hl[lane + 64]; r2 = hr[lane + 64]; k2 = kp[lane + 64]; }

        float4 qa = q4[lane];
        float acc = (qa.x + l0.x) * (k0.x + r0.x) + (qa.y + l0.y) * (k0.y + r0.y)
                  + (qa.z + l0.z) * (k0.z + r0.z) + (qa.w + l0.w) * (k0.w + r0.w);
        float4 qb = q4[lane + 32];
        acc += (qb.x + l1.x) * (k1.x + r1.x) + (qb.y + l1.y) * (k1.y + r1.y)
             + (qb.z + l1.z) * (k1.z + r1.z) + (qb.w + l1.w) * (k1.w + r1.w);
        if (has_c) {
            float4 qc = q4[lane + 64];
            acc += (qc.x + l2.x) * (k2.x + r2.x) + (qc.y + l2.y) * (k2.y + r2.y)
                 + (qc.z + l2.z) * (k2.z + r2.z) + (qc.w + l2.w) * (k2.w + r2.w);
        }
#pragma unroll
        for (int o = 16; o > 0; o >>= 1)
            acc += __shfl_xor_sync(0xffffffffu, acc, o);
        if (lane == 0) scores_s[j] = acc;
    }
    __syncthreads();

    // ---- p = softmax(scores); attn = softmax(1000*p); clip is a no-op.
    // p_max = 1/sum exactly (max exp term is 1): 1000*(p-p_max) = 1000*inv*(e-1)
    // Build an ORDERED compact list of significant j (deterministic).
    if (w == 0) {
        float s0 = scores_s[lane],      s1 = scores_s[lane + 32];
        float s2 = scores_s[lane + 64], s3 = scores_s[lane + 96];
        float m = fmaxf(fmaxf(s0, s1), fmaxf(s2, s3));
#pragma unroll
        for (int o = 16; o > 0; o >>= 1)
            m = fmaxf(m, __shfl_xor_sync(0xffffffffu, m, o));
        float e0 = expf(s0 - m), e1 = expf(s1 - m);
        float e2 = expf(s2 - m), e3 = expf(s3 - m);
        float sum = e0 + e1 + e2 + e3;
#pragma unroll
        for (int o = 16; o > 0; o >>= 1)
            sum += __shfl_xor_sync(0xffffffffu, sum, o);
        float inv = 1.f / sum;
        float a0 = expf(1000.f * inv * (e0 - 1.f));
        float a1 = expf(1000.f * inv * (e1 - 1.f));
        float a2 = expf(1000.f * inv * (e2 - 1.f));
        float a3 = expf(1000.f * inv * (e3 - 1.f));
        float sum2 = a0 + a1 + a2 + a3;
#pragma unroll
        for (int o = 16; o > 0; o >>= 1)
            sum2 += __shfl_xor_sync(0xffffffffu, sum2, o);
        float inv2 = 1.f / sum2;

        float av[4] = {a0 * inv2, a1 * inv2, a2 * inv2, a3 * inv2};
        int base = 0;
#pragma unroll
        for (int qd = 0; qd < 4; qd++) {
            bool f = av[qd] > 1e-12f;
            unsigned mask = __ballot_sync(0xffffffffu, f);
            int pos = base + __popc(mask & ((1u << lane) - 1u));
            if (f) { listj_s[pos] = qd * 32 + lane; listw_s[pos] = av[qd]; }
            base += __popc(mask);
        }
        if (lane == 0) cnt_s = base;
    }
    __syncthreads();

    // ---- output: out[b,i,d] = sum over significant j of a_j*(v[j,d]+hR[j,i,d])
    const float* vg  = g_qkv + (size_t)(2 * Bq * T + b * T) * D;
    const float* hRs = hR + ((size_t)b * T * T + i) * D;
    const int cnt = cnt_s;
#pragma unroll
    for (int rep = 0; rep < 2; rep++) {
        int d = tid + rep * 256;
        if (d < D) {
            float acc = 0.f;
            for (int t = 0; t < cnt; t++) {
                int   j = listj_s[t];
                float a = listw_s[t];
                acc += a * (vg[j * D + d] + hRs[(size_t)j * T * D + d]);
            }
            out[(b * T + i) * D + d] = acc;
        }
    }
}

// ---------------------------------------------------------------------------
extern "C" void kernel_launch(void* const* d_in, const int* in_sizes, int n_in,
                              void* d_out, int out_size)
{
    const float* query = (const float*)d_in[0];
    const float* key   = (const float*)d_in[1];
    const float* value = (const float*)d_in[2];
    const float* hL    = (const float*)d_in[3];
    const float* hR    = (const float*)d_in[4];
    const float* WQ    = (const float*)d_in[5];
    const float* bQ    = (const float*)d_in[6];
    const float* WK    = (const float*)d_in[7];
    const float* bK    = (const float*)d_in[8];
    float* out = (float*)d_out;

    // 1536 rows x 300 cols: 48 row tiles x 10 col tiles of 32 = 480 CTAs
    proj_kernel<<<dim3(10, 48), 128>>>(query, key, value, WQ, bQ, WK, bK);
    attn_kernel<<<Bq * T, 256>>>(hL, hR, out);
}

// round 13
// speedup vs baseline: 1.0665x; 1.0665x over previous
#include <cuda_runtime.h>
#include <cstdint>

#define Bq 4
#define T 128
#define D 300
#define D4 75            // D / 4 (float4 count per row)

// Scratch for projected q (rows 0..511), k (512..1023), v (1024..1535)
__device__ __align__(16) float g_qkv[3 * Bq * T * D];
// Compact significant-j lists produced by attn_mix, consumed by attn_out
__device__ int   g_cnt[Bq * T];
__device__ int   g_listj[Bq * T * 128];
__device__ float g_listw[Bq * T * 128];

// ---------------------------------------------------------------------------
// Kernel 1: q/k projection GEMM (v deferred into attn_mix).
// Round-10 proven shape: 32x32 tiles, 128 threads, 4x2 microtile, k-chunk 32,
// double-buffered, swizzled smem. Grid (10, 32) = 320 CTAs (rows 0..1023).
// ---------------------------------------------------------------------------
__global__ __launch_bounds__(128) void proj_qk_kernel(
    const float* __restrict__ query, const float* __restrict__ key,
    const float* __restrict__ WQ, const float* __restrict__ bQ,
    const float* __restrict__ WK, const float* __restrict__ bK)
{
    __shared__ float A_s[2][32][36];
    __shared__ float W_s[2][32][36];

    const int row0 = blockIdx.y * 32;
    const int col0 = blockIdx.x * 32;
    const int tid  = threadIdx.x;
    const int tx   = tid & 15;
    const int ty   = tid >> 4;

    const int sel = row0 >> 9;    // 0: query, 1: key
    const float* Ap = (sel == 0) ? query : key;
    const float* Wp = (sel == 0) ? WQ : WK;
    const float* bp = (sel == 0) ? bQ : bK;
    const int arow0 = row0 & 511;

    const int lm = tid >> 3;          // 0..15
    const int lk = (tid & 7) * 4;     // 0,4,..,28

    const int NC = (D + 31) / 32;
    float4 a_r[2], w_r[2];

    auto fetch = [&](int k0) {
        bool kv = (k0 + lk) < D;
#pragma unroll
        for (int p = 0; p < 2; p++) {
            int r = lm + p * 16;
            a_r[p] = kv ? *(const float4*)&Ap[(arow0 + r) * D + k0 + lk]
                        : make_float4(0.f, 0.f, 0.f, 0.f);
            int gc = col0 + r;
            w_r[p] = (kv && gc < D) ? *(const float4*)&Wp[gc * D + k0 + lk]
                                    : make_float4(0.f, 0.f, 0.f, 0.f);
        }
    };
    auto store = [&](int buf) {
#pragma unroll
        for (int p = 0; p < 2; p++) {
            int r   = lm + p * 16;
            int col = (r + lk) & 31;
            A_s[buf][lk + 0][col] = a_r[p].x; A_s[buf][lk + 1][col] = a_r[p].y;
            A_s[buf][lk + 2][col] = a_r[p].z; A_s[buf][lk + 3][col] = a_r[p].w;
            W_s[buf][lk + 0][col] = w_r[p].x; W_s[buf][lk + 1][col] = w_r[p].y;
            W_s[buf][lk + 2][col] = w_r[p].z; W_s[buf][lk + 3][col] = w_r[p].w;
        }
    };

    float acc[4][2];
#pragma unroll
    for (int r = 0; r < 4; r++) { acc[r][0] = 0.f; acc[r][1] = 0.f; }

    fetch(0);
    store(0);
    __syncthreads();

    for (int ch = 0; ch < NC; ch++) {
        const int buf = ch & 1;
        if (ch + 1 < NC) fetch((ch + 1) * 32);
#pragma unroll
        for (int e = 0; e < 32; e++) {
            const int off = e & ~3;
            float4 av = *(const float4*)&A_s[buf][e][(ty * 4 + off) & 31];
            float2 wv = *(const float2*)&W_s[buf][e][(tx * 2 + off) & 31];
            acc[0][0] += av.x * wv.x; acc[0][1] += av.x * wv.y;
            acc[1][0] += av.y * wv.x; acc[1][1] += av.y * wv.y;
            acc[2][0] += av.z * wv.x; acc[2][1] += av.z * wv.y;
            acc[3][0] += av.w * wv.x; acc[3][1] += av.w * wv.y;
        }
        if (ch + 1 < NC) store(1 - buf);
        __syncthreads();
    }

#pragma unroll
    for (int r = 0; r < 4; r++) {
        int gr = row0 + ty * 4 + r;
#pragma unroll
        for (int c = 0; c < 2; c++) {
            int gcol = col0 + tx * 2 + c;
            if (gcol < D) g_qkv[gr * D + gcol] = acc[r][c] + bp[gcol];
        }
    }
}

// ---------------------------------------------------------------------------
// Kernel 2: mixed grid, 592 CTAs x 256 threads (exactly one 4-CTA/SM wave).
//  - blocks [0,512): scoring + softmax for (b,i); compact j-list -> global.
//  - blocks [512,592): v projection (value @ WK^T + bK) into g_qkv rows
//    1024..1535, riding the idle issue slots of the DRAM-bound scoring.
// ---------------------------------------------------------------------------
#define POOL_FLOATS (2 * 32 * 68 + 2 * 32 * 36)   // v-proj A_s + W_s

__global__ __launch_bounds__(256, 4) void attn_mix_kernel(
    const float* __restrict__ hL, const float* __restrict__ hR,
    const float* __restrict__ value,
    const float* __restrict__ WK, const float* __restrict__ bK)
{
    __shared__ float pool[POOL_FLOATS];

    const int tid  = threadIdx.x;
    const int lane = tid & 31;
    const int w    = tid >> 5;

    if (blockIdx.x >= 512) {
        // ================= v-projection branch =================
        const int e0   = blockIdx.x - 512;   // 0..79
        const int row0 = (e0 & 7) * 64;      // within v's 512 rows
        const int col0 = (e0 >> 3) * 32;

        float* A_s = pool;                   // [2][32][68]
        float* W_s = pool + 2 * 32 * 68;     // [2][32][36]
#define AS(b, k, r) A_s[(((b) * 32 + (k)) * 68) + (r)]
#define WS(b, k, r) W_s[(((b) * 32 + (k)) * 36) + (r)]

        const int tx = tid & 15;    // 16 col groups x 2 cols
        const int ty = tid >> 4;    // 16 row groups x 4 rows

        const int NC = (D + 31) / 32;
        float4 a_r[2], w_r;
        const int ar  = -1;         // silence unused warnings pattern
        (void)ar;

        auto fetch = [&](int k0) {
#pragma unroll
            for (int p = 0; p < 2; p++) {
                int idx = p * 256 + tid;
                int r = idx & 63, kk = k0 + ((idx >> 6) << 2);
                a_r[p] = (kk < D) ? *(const float4*)&value[(row0 + r) * D + kk]
                                  : make_float4(0.f, 0.f, 0.f, 0.f);
            }
            int wr = tid & 31, kk = k0 + ((tid >> 5) << 2);
            int gc = col0 + wr;
            w_r = (kk < D && gc < D) ? *(const float4*)&WK[gc * D + kk]
                                     : make_float4(0.f, 0.f, 0.f, 0.f);
        };
        auto store = [&](int buf) {
#pragma unroll
            for (int p = 0; p < 2; p++) {
                int idx = p * 256 + tid;
                int r = idx & 63, ee = (idx >> 6) << 2;
                AS(buf, ee + 0, r) = a_r[p].x; AS(buf, ee + 1, r) = a_r[p].y;
                AS(buf, ee + 2, r) = a_r[p].z; AS(buf, ee + 3, r) = a_r[p].w;
            }
            int wr = tid & 31, ee = (tid >> 5) << 2;
            WS(buf, ee + 0, wr) = w_r.x; WS(buf, ee + 1, wr) = w_r.y;
            WS(buf, ee + 2, wr) = w_r.z; WS(buf, ee + 3, wr) = w_r.w;
        };

        float acc[4][2];
#pragma unroll
        for (int r = 0; r < 4; r++) { acc[r][0] = 0.f; acc[r][1] = 0.f; }

        fetch(0);
        store(0);
        __syncthreads();

        for (int ch = 0; ch < NC; ch++) {
            const int buf = ch & 1;
            if (ch + 1 < NC) fetch((ch + 1) * 32);
#pragma unroll
            for (int ee = 0; ee < 32; ee++) {
                float4 av = *(const float4*)&AS(buf, ee, ty * 4);
                float2 wv = *(const float2*)&WS(buf, ee, tx * 2);
                acc[0][0] += av.x * wv.x; acc[0][1] += av.x * wv.y;
                acc[1][0] += av.y * wv.x; acc[1][1] += av.y * wv.y;
                acc[2][0] += av.z * wv.x; acc[2][1] += av.z * wv.y;
                acc[3][0] += av.w * wv.x; acc[3][1] += av.w * wv.y;
            }
            if (ch + 1 < NC) store(1 - buf);
            __syncthreads();
        }

#pragma unroll
        for (int r = 0; r < 4; r++) {
            int gr = 2 * Bq * T + row0 + ty * 4 + r;    // v rows 1024..1535
#pragma unroll
            for (int c = 0; c < 2; c++) {
                int gcol = col0 + tx * 2 + c;
                if (gcol < D) g_qkv[gr * D + gcol] = acc[r][c] + bK[gcol];
            }
        }
        return;
#undef AS
#undef WS
    }

    // ================= scoring branch =================
    float* q_s      = pool;          // 304 floats
    float* scores_s = pool + 304;    // 128 floats

    const int bi = blockIdx.x;
    const int b  = bi >> 7;
    const int i  = bi & 127;

    const float4* qkv4 = (const float4*)g_qkv;

    if (tid < D4) ((float4*)q_s)[tid] = qkv4[(b * T + i) * D4 + tid];
    __syncthreads();

    const float4* q4 = (const float4*)q_s;
    const bool has_c = (lane < D4 - 64);

    const float4* hL4 = (const float4*)hL + (size_t)(b * T + i) * T * D4;
    const float4* hRb = (const float4*)hR + ((size_t)b * T * T + i) * D4;
    const float4* k4b = qkv4 + (Bq * T + b * T) * D4;

#pragma unroll 2
    for (int jj = 0; jj < 16; jj++) {
        const int j = w * 16 + jj;
        const float4* hl = hL4 + j * D4;
        const float4* hr = hRb + (size_t)j * T * D4;
        const float4* kp = k4b + j * D4;

        float4 l0 = hl[lane],      r0 = hr[lane],      k0 = kp[lane];
        float4 l1 = hl[lane + 32], r1 = hr[lane + 32], k1 = kp[lane + 32];
        float4 l2, r2, k2;
        if (has_c) { l2 = hl[lane + 64]; r2 = hr[lane + 64]; k2 = kp[lane + 64]; }

        float4 qa = q4[lane];
        float acc = (qa.x + l0.x) * (k0.x + r0.x) + (qa.y + l0.y) * (k0.y + r0.y)
                  + (qa.z + l0.z) * (k0.z + r0.z) + (qa.w + l0.w) * (k0.w + r0.w);
        float4 qb = q4[lane + 32];
        acc += (qb.x + l1.x) * (k1.x + r1.x) + (qb.y + l1.y) * (k1.y + r1.y)
             + (qb.z + l1.z) * (k1.z + r1.z) + (qb.w + l1.w) * (k1.w + r1.w);
        if (has_c) {
            float4 qc = q4[lane + 64];
            acc += (qc.x + l2.x) * (k2.x + r2.x) + (qc.y + l2.y) * (k2.y + r2.y)
                 + (qc.z + l2.z) * (k2.z + r2.z) + (qc.w + l2.w) * (k2.w + r2.w);
        }
#pragma unroll
        for (int o = 16; o > 0; o >>= 1)
            acc += __shfl_xor_sync(0xffffffffu, acc, o);
        if (lane == 0) scores_s[j] = acc;
    }
    __syncthreads();

    // p = softmax(scores); attn = softmax(1000*p); clip no-op.
    // p_max = 1/sum exactly: 1000*(p - p_max) = 1000*inv*(e - 1).
    // Ordered compact list of significant j -> global.
    if (w == 0) {
        float s0 = scores_s[lane],      s1 = scores_s[lane + 32];
        float s2 = scores_s[lane + 64], s3 = scores_s[lane + 96];
        float m = fmaxf(fmaxf(s0, s1), fmaxf(s2, s3));
#pragma unroll
        for (int o = 16; o > 0; o >>= 1)
            m = fmaxf(m, __shfl_xor_sync(0xffffffffu, m, o));
        float e0 = expf(s0 - m), e1 = expf(s1 - m);
        float e2 = expf(s2 - m), e3 = expf(s3 - m);
        float sum = e0 + e1 + e2 + e3;
#pragma unroll
        for (int o = 16; o > 0; o >>= 1)
            sum += __shfl_xor_sync(0xffffffffu, sum, o);
        float inv = 1.f / sum;
        float a0 = expf(1000.f * inv * (e0 - 1.f));
        float a1 = expf(1000.f * inv * (e1 - 1.f));
        float a2 = expf(1000.f * inv * (e2 - 1.f));
        float a3 = expf(1000.f * inv * (e3 - 1.f));
        float sum2 = a0 + a1 + a2 + a3;
#pragma unroll
        for (int o = 16; o > 0; o >>= 1)
            sum2 += __shfl_xor_sync(0xffffffffu, sum2, o);
        float inv2 = 1.f / sum2;

        float av[4] = {a0 * inv2, a1 * inv2, a2 * inv2, a3 * inv2};
        int base = 0;
#pragma unroll
        for (int qd = 0; qd < 4; qd++) {
            bool f = av[qd] > 1e-12f;
            unsigned mask = __ballot_sync(0xffffffffu, f);
            int pos = base + __popc(mask & ((1u << lane) - 1u));
            if (f) {
                g_listj[bi * 128 + pos] = qd * 32 + lane;
                g_listw[bi * 128 + pos] = av[qd];
            }
            base += __popc(mask);
        }
        if (lane == 0) g_cnt[bi] = base;
    }
}

// ---------------------------------------------------------------------------
// Kernel 3: output gather. out[b,i,d] = sum over significant j of
// a_j * (v[b,j,d] + hR[b,j,i,d]). v guaranteed ready (kernel boundary).
// ---------------------------------------------------------------------------
__global__ __launch_bounds__(256) void attn_out_kernel(
    const float* __restrict__ hR, float* __restrict__ out)
{
    __shared__ int   lj[128];
    __shared__ float lw[128];
    __shared__ int   cnt_sh;

    const int tid = threadIdx.x;
    const int bi  = blockIdx.x;
    const int b   = bi >> 7;
    const int i   = bi & 127;

    if (tid == 0) cnt_sh = g_cnt[bi];
    __syncthreads();
    const int cnt = cnt_sh;
    if (tid < cnt) {
        lj[tid] = g_listj[bi * 128 + tid];
        lw[tid] = g_listw[bi * 128 + tid];
    }
    __syncthreads();

    const float* vg  = g_qkv + (size_t)(2 * Bq * T + b * T) * D;
    const float* hRs = hR + ((size_t)b * T * T + i) * D;
#pragma unroll
    for (int rep = 0; rep < 2; rep++) {
        int d = tid + rep * 256;
        if (d < D) {
            float acc = 0.f;
            for (int t = 0; t < cnt; t++) {
                int   j = lj[t];
                float a = lw[t];
                acc += a * (vg[j * D + d] + hRs[(size_t)j * T * D + d]);
            }
            out[(b * T + i) * D + d] = acc;
        }
    }
}

// ---------------------------------------------------------------------------
extern "C" void kernel_launch(void* const* d_in, const int* in_sizes, int n_in,
                              void* d_out, int out_size)
{
    const float* query = (const float*)d_in[0];
    const float* key   = (const float*)d_in[1];
    const float* value = (const float*)d_in[2];
    const float* hL    = (const float*)d_in[3];
    const float* hR    = (const float*)d_in[4];
    const float* WQ    = (const float*)d_in[5];
    const float* bQ    = (const float*)d_in[6];
    const float* WK    = (const float*)d_in[7];
    const float* bK    = (const float*)d_in[8];
    float* out = (float*)d_out;

    // q,k: 1024 rows x 300 cols = 32 row tiles x 10 col tiles
    proj_qk_kernel<<<dim3(10, 32), 128>>>(query, key, WQ, bQ, WK, bK);
    // 512 scoring CTAs + 80 v-projection CTAs = one full 4-CTA/SM wave
    attn_mix_kernel<<<592, 256>>>(hL, hR, value, WK, bK);
    attn_out_kernel<<<Bq * T, 256>>>(hR, out);
}